// round 12
// baseline (speedup 1.0000x reference)
#include <cuda_runtime.h>
#include <math.h>

#define BSZ 1024
#define DD  256
#define NN  200000
#define STEPS 3

// ---------------- device state (allocation-free scratch) ----------------
__device__ float g_qstar[BSZ * 2 * DD];   // current q_star [B, 2D]
__device__ float g_h[BSZ * DD];
__device__ float g_c[BSZ * DD];
__device__ float g_gates[BSZ * 4 * DD];
__device__ int   g_segstart[BSZ + 1];     // row range per segment

// ---------------- init: q_star <- input, h=c=0 ----------------
__global__ void k_init(const float* __restrict__ qs) {
    int i = blockIdx.x * blockDim.x + threadIdx.x;
    if (i < BSZ * 2 * DD) g_qstar[i] = qs[i];
    if (i < BSZ * DD) { g_h[i] = 0.f; g_c[i] = 0.f; }
}

// ---------------- segment boundaries via binary search ------------------
__global__ void k_seg(const int* __restrict__ batch) {
    int b = blockIdx.x * blockDim.x + threadIdx.x;
    if (b > BSZ) return;
    int lo = 0, hi = NN;
    while (lo < hi) {
        int mid = (lo + hi) >> 1;
        if (batch[mid] < b) lo = mid + 1; else hi = mid;
    }
    g_segstart[b] = lo;
}

// ---------------- GEMM: gates = qstar@W_ih^T + h@W_hh^T + biases --------
__global__ void k_gemm_gates(const float* __restrict__ W1,
                             const float* __restrict__ W2,
                             const float* __restrict__ b1,
                             const float* __restrict__ b2) {
    __shared__ float As[16][68];
    __shared__ float Bs[16][68];
    int tid  = threadIdx.x;
    int row0 = blockIdx.y * 64;
    int col0 = blockIdx.x * 64;
    int lr = tid >> 2;
    int lc = (tid & 3) << 2;
    int tx = tid & 15, ty = tid >> 4;

    float acc[4][4];
#pragma unroll
    for (int i = 0; i < 4; i++)
#pragma unroll
        for (int j = 0; j < 4; j++) acc[i][j] = 0.f;

#pragma unroll
    for (int phase = 0; phase < 2; phase++) {
        const float* A = phase ? g_h : g_qstar;
        const float* W = phase ? W2 : W1;
        const int K = phase ? 256 : 512;
        for (int k0 = 0; k0 < K; k0 += 16) {
            float4 av = *(const float4*)&A[(size_t)(row0 + lr) * K + k0 + lc];
            float4 wv = *(const float4*)&W[(size_t)(col0 + lr) * K + k0 + lc];
            As[lc + 0][lr] = av.x; As[lc + 1][lr] = av.y;
            As[lc + 2][lr] = av.z; As[lc + 3][lr] = av.w;
            Bs[lc + 0][lr] = wv.x; Bs[lc + 1][lr] = wv.y;
            Bs[lc + 2][lr] = wv.z; Bs[lc + 3][lr] = wv.w;
            __syncthreads();
#pragma unroll
            for (int kk = 0; kk < 16; kk++) {
                float a[4], bb[4];
#pragma unroll
                for (int i = 0; i < 4; i++) a[i] = As[kk][ty * 4 + i];
#pragma unroll
                for (int j = 0; j < 4; j++) bb[j] = Bs[kk][tx * 4 + j];
#pragma unroll
                for (int i = 0; i < 4; i++)
#pragma unroll
                    for (int j = 0; j < 4; j++) acc[i][j] += a[i] * bb[j];
            }
            __syncthreads();
        }
    }
#pragma unroll
    for (int i = 0; i < 4; i++) {
        int r = row0 + ty * 4 + i;
#pragma unroll
        for (int j = 0; j < 4; j++) {
            int c = col0 + tx * 4 + j;
            g_gates[(size_t)r * 1024 + c] = acc[i][j] + b1[c] + b2[c];
        }
    }
}

// ------- fused LSTM-cell + single-pass attention: one block/segment -----
__global__ void __launch_bounds__(256) k_attn(const float* __restrict__ x) {
    int b = blockIdx.x;
    int tid = threadIdx.x;
    int w = tid >> 5, lane = tid & 31;

    __shared__ float s_q[DD];
    __shared__ float s_acc[8][DD];
    __shared__ float s_mx[8];
    __shared__ float s_sm[8];

    // ---- LSTM cell for this segment's batch row (tid == gate dim d) ----
    {
        size_t gb = (size_t)b * 1024;
        float ig = g_gates[gb + tid];
        float fg = g_gates[gb + 256 + tid];
        float gg = g_gates[gb + 512 + tid];
        float og = g_gates[gb + 768 + tid];
        float i = 1.f / (1.f + expf(-ig));
        float f = 1.f / (1.f + expf(-fg));
        float g = tanhf(gg);
        float o = 1.f / (1.f + expf(-og));
        float c = f * g_c[b * DD + tid] + i * g;
        float h = o * tanhf(c);
        g_c[b * DD + tid] = c;
        g_h[b * DD + tid] = h;
        g_qstar[(size_t)b * 512 + tid] = h;   // q part of next q_star
        s_q[tid] = h;
    }
    __syncthreads();

    int r0 = g_segstart[b];
    int r1 = g_segstart[b + 1];

    float4 q0 = *(const float4*)&s_q[4 * lane];
    float4 q1 = *(const float4*)&s_q[128 + 4 * lane];

    float wmax = -INFINITY, wsum = 0.f;
    float a0x = 0.f, a0y = 0.f, a0z = 0.f, a0w = 0.f;
    float a1x = 0.f, a1y = 0.f, a1z = 0.f, a1w = 0.f;

    // ---- online softmax, 2 rows per warp-iteration ----
    for (int n = r0 + 2 * w; n < r1; n += 16) {
        const float4* xra = (const float4*)(x + (size_t)n * DD);
        float4 xa0 = xra[lane];
        float4 xa1 = xra[lane + 32];
        bool two = (n + 1 < r1);
        float4 xb0 = make_float4(0.f, 0.f, 0.f, 0.f);
        float4 xb1 = xb0;
        float sb = -INFINITY;
        if (two) {
            const float4* xrb = (const float4*)(x + (size_t)(n + 1) * DD);
            xb0 = xrb[lane];
            xb1 = xrb[lane + 32];
            sb = xb0.x * q0.x + xb0.y * q0.y + xb0.z * q0.z + xb0.w * q0.w
               + xb1.x * q1.x + xb1.y * q1.y + xb1.z * q1.z + xb1.w * q1.w;
        }
        float sa = xa0.x * q0.x + xa0.y * q0.y + xa0.z * q0.z + xa0.w * q0.w
                 + xa1.x * q1.x + xa1.y * q1.y + xa1.z * q1.z + xa1.w * q1.w;
#pragma unroll
        for (int o = 16; o; o >>= 1) {
            sa += __shfl_xor_sync(0xffffffffu, sa, o);
            sb += __shfl_xor_sync(0xffffffffu, sb, o);
        }
        if (!two) sb = -INFINITY;  // butterfly of -inf stays -inf anyway

        float mnew = fmaxf(wmax, fmaxf(sa, sb));
        if (mnew > wmax) {
            float sc = __expf(wmax - mnew);   // 0 on first iteration
            wsum *= sc;
            a0x *= sc; a0y *= sc; a0z *= sc; a0w *= sc;
            a1x *= sc; a1y *= sc; a1z *= sc; a1w *= sc;
            wmax = mnew;
        }
        float pa = __expf(sa - wmax);
        float pb = __expf(sb - wmax);        // 0 when !two
        wsum += pa + pb;
        a0x += pa * xa0.x + pb * xb0.x; a0y += pa * xa0.y + pb * xb0.y;
        a0z += pa * xa0.z + pb * xb0.z; a0w += pa * xa0.w + pb * xb0.w;
        a1x += pa * xa1.x + pb * xb1.x; a1y += pa * xa1.y + pb * xb1.y;
        a1z += pa * xa1.z + pb * xb1.z; a1w += pa * xa1.w + pb * xb1.w;
    }

    // stash per-warp state
    int c0 = 4 * lane;
    s_acc[w][c0 + 0] = a0x; s_acc[w][c0 + 1] = a0y;
    s_acc[w][c0 + 2] = a0z; s_acc[w][c0 + 3] = a0w;
    s_acc[w][128 + c0 + 0] = a1x; s_acc[w][128 + c0 + 1] = a1y;
    s_acc[w][128 + c0 + 2] = a1z; s_acc[w][128 + c0 + 3] = a1w;
    if (lane == 0) { s_mx[w] = wmax; s_sm[w] = wsum; }
    __syncthreads();

    // combine 8 warps; tid == output column d
    float M = -INFINITY;
#pragma unroll
    for (int i = 0; i < 8; i++) M = fmaxf(M, s_mx[i]);
    if (M == -INFINITY) M = 0.f;   // empty-segment guard (matches reference)

    float total = 0.f, r = 0.f;
#pragma unroll
    for (int i = 0; i < 8; i++) {
        float f = __expf(s_mx[i] - M);   // exp(-inf - M) = 0 for idle warps
        total += s_sm[i] * f;
        r += s_acc[i][tid] * f;
    }
    g_qstar[(size_t)b * 512 + 256 + tid] = r / (total + 1e-16f);
}

// ---------------- final copy ---------------------------------------------
__global__ void k_out(float* __restrict__ out) {
    int i = blockIdx.x * blockDim.x + threadIdx.x;
    if (i < BSZ * 2 * DD) out[i] = g_qstar[i];
}

extern "C" void kernel_launch(void* const* d_in, const int* in_sizes, int n_in,
                              void* d_out, int out_size) {
    const float* x     = (const float*)d_in[0];
    const int*   batch = (const int*)d_in[2];
    const float* qs    = (const float*)d_in[3];
    const float* W_ih  = (const float*)d_in[4];
    const float* W_hh  = (const float*)d_in[5];
    const float* b_ih  = (const float*)d_in[6];
    const float* b_hh  = (const float*)d_in[7];

    k_init<<<2048, 256>>>(qs);
    k_seg<<<5, 256>>>(batch);

    dim3 gg(16, 16);
    for (int s = 0; s < STEPS; s++) {
        k_gemm_gates<<<gg, 256>>>(W_ih, W_hh, b_ih, b_hh);
        k_attn<<<BSZ, 256>>>(x);
    }
    k_out<<<2048, 256>>>((float*)d_out);
}

// round 13
// speedup vs baseline: 1.0050x; 1.0050x over previous
#include <cuda_runtime.h>
#include <math.h>

#define BSZ 1024
#define DD  256
#define NN  200000
#define STEPS 3

// ---------------- device state (allocation-free scratch) ----------------
__device__ float g_qstar[BSZ * 2 * DD];   // current q_star [B, 2D]
__device__ float g_h[BSZ * DD];
__device__ float g_c[BSZ * DD];
__device__ float g_gates[BSZ * 4 * DD];
__device__ int   g_segstart[BSZ + 1];     // row range per segment

// ---------------- init: q_star <- input, h=c=0 ----------------
__global__ void k_init(const float* __restrict__ qs) {
    int i = blockIdx.x * blockDim.x + threadIdx.x;
    if (i < BSZ * 2 * DD) g_qstar[i] = qs[i];
    if (i < BSZ * DD) { g_h[i] = 0.f; g_c[i] = 0.f; }
}

// ---------------- segment boundaries via binary search ------------------
__global__ void k_seg(const int* __restrict__ batch) {
    int b = blockIdx.x * blockDim.x + threadIdx.x;
    if (b > BSZ) return;
    int lo = 0, hi = NN;
    while (lo < hi) {
        int mid = (lo + hi) >> 1;
        if (batch[mid] < b) lo = mid + 1; else hi = mid;
    }
    g_segstart[b] = lo;
}

// ---------------- GEMM: gates = qstar@W_ih^T + h@W_hh^T + biases --------
__global__ void k_gemm_gates(const float* __restrict__ W1,
                             const float* __restrict__ W2,
                             const float* __restrict__ b1,
                             const float* __restrict__ b2) {
    __shared__ float As[16][68];
    __shared__ float Bs[16][68];
    int tid  = threadIdx.x;
    int row0 = blockIdx.y * 64;
    int col0 = blockIdx.x * 64;
    int lr = tid >> 2;
    int lc = (tid & 3) << 2;
    int tx = tid & 15, ty = tid >> 4;

    float acc[4][4];
#pragma unroll
    for (int i = 0; i < 4; i++)
#pragma unroll
        for (int j = 0; j < 4; j++) acc[i][j] = 0.f;

#pragma unroll
    for (int phase = 0; phase < 2; phase++) {
        const float* A = phase ? g_h : g_qstar;
        const float* W = phase ? W2 : W1;
        const int K = phase ? 256 : 512;
        for (int k0 = 0; k0 < K; k0 += 16) {
            float4 av = *(const float4*)&A[(size_t)(row0 + lr) * K + k0 + lc];
            float4 wv = *(const float4*)&W[(size_t)(col0 + lr) * K + k0 + lc];
            As[lc + 0][lr] = av.x; As[lc + 1][lr] = av.y;
            As[lc + 2][lr] = av.z; As[lc + 3][lr] = av.w;
            Bs[lc + 0][lr] = wv.x; Bs[lc + 1][lr] = wv.y;
            Bs[lc + 2][lr] = wv.z; Bs[lc + 3][lr] = wv.w;
            __syncthreads();
#pragma unroll
            for (int kk = 0; kk < 16; kk++) {
                float a[4], bb[4];
#pragma unroll
                for (int i = 0; i < 4; i++) a[i] = As[kk][ty * 4 + i];
#pragma unroll
                for (int j = 0; j < 4; j++) bb[j] = Bs[kk][tx * 4 + j];
#pragma unroll
                for (int i = 0; i < 4; i++)
#pragma unroll
                    for (int j = 0; j < 4; j++) acc[i][j] += a[i] * bb[j];
            }
            __syncthreads();
        }
    }
#pragma unroll
    for (int i = 0; i < 4; i++) {
        int r = row0 + ty * 4 + i;
#pragma unroll
        for (int j = 0; j < 4; j++) {
            int c = col0 + tx * 4 + j;
            g_gates[(size_t)r * 1024 + c] = acc[i][j] + b1[c] + b2[c];
        }
    }
}

// ------- fused LSTM-cell + single-pass attention: one block/segment -----
__global__ void __launch_bounds__(256) k_attn(const float* __restrict__ x) {
    int b = blockIdx.x;
    int tid = threadIdx.x;
    int w = tid >> 5, lane = tid & 31;

    __shared__ float s_q[DD];
    __shared__ float s_acc[8][DD];
    __shared__ float s_mx[8];
    __shared__ float s_sm[8];

    // ---- LSTM cell for this segment's batch row (tid == gate dim d) ----
    {
        size_t gb = (size_t)b * 1024;
        float ig = g_gates[gb + tid];
        float fg = g_gates[gb + 256 + tid];
        float gg = g_gates[gb + 512 + tid];
        float og = g_gates[gb + 768 + tid];
        float i = 1.f / (1.f + expf(-ig));
        float f = 1.f / (1.f + expf(-fg));
        float g = tanhf(gg);
        float o = 1.f / (1.f + expf(-og));
        float c = f * g_c[b * DD + tid] + i * g;
        float h = o * tanhf(c);
        g_c[b * DD + tid] = c;
        g_h[b * DD + tid] = h;
        g_qstar[(size_t)b * 512 + tid] = h;   // q part of next q_star
        s_q[tid] = h;
    }
    __syncthreads();

    int r0 = g_segstart[b];
    int r1 = g_segstart[b + 1];

    float4 q0 = *(const float4*)&s_q[4 * lane];
    float4 q1 = *(const float4*)&s_q[128 + 4 * lane];

    float wmax = -INFINITY, wsum = 0.f;
    float a0x = 0.f, a0y = 0.f, a0z = 0.f, a0w = 0.f;
    float a1x = 0.f, a1y = 0.f, a1z = 0.f, a1w = 0.f;

    // ---- online softmax, 2 rows per warp-iteration ----
    for (int n = r0 + 2 * w; n < r1; n += 16) {
        const float4* xra = (const float4*)(x + (size_t)n * DD);
        float4 xa0 = xra[lane];
        float4 xa1 = xra[lane + 32];
        bool two = (n + 1 < r1);
        float4 xb0 = make_float4(0.f, 0.f, 0.f, 0.f);
        float4 xb1 = xb0;
        float sb = -INFINITY;
        if (two) {
            const float4* xrb = (const float4*)(x + (size_t)(n + 1) * DD);
            xb0 = xrb[lane];
            xb1 = xrb[lane + 32];
            sb = xb0.x * q0.x + xb0.y * q0.y + xb0.z * q0.z + xb0.w * q0.w
               + xb1.x * q1.x + xb1.y * q1.y + xb1.z * q1.z + xb1.w * q1.w;
        }
        float sa = xa0.x * q0.x + xa0.y * q0.y + xa0.z * q0.z + xa0.w * q0.w
                 + xa1.x * q1.x + xa1.y * q1.y + xa1.z * q1.z + xa1.w * q1.w;
#pragma unroll
        for (int o = 16; o; o >>= 1) {
            sa += __shfl_xor_sync(0xffffffffu, sa, o);
            sb += __shfl_xor_sync(0xffffffffu, sb, o);
        }
        if (!two) sb = -INFINITY;  // butterfly of -inf stays -inf anyway

        float mnew = fmaxf(wmax, fmaxf(sa, sb));
        if (mnew > wmax) {
            float sc = __expf(wmax - mnew);   // 0 on first iteration
            wsum *= sc;
            a0x *= sc; a0y *= sc; a0z *= sc; a0w *= sc;
            a1x *= sc; a1y *= sc; a1z *= sc; a1w *= sc;
            wmax = mnew;
        }
        float pa = __expf(sa - wmax);
        float pb = __expf(sb - wmax);        // 0 when !two
        wsum += pa + pb;
        a0x += pa * xa0.x + pb * xb0.x; a0y += pa * xa0.y + pb * xb0.y;
        a0z += pa * xa0.z + pb * xb0.z; a0w += pa * xa0.w + pb * xb0.w;
        a1x += pa * xa1.x + pb * xb1.x; a1y += pa * xa1.y + pb * xb1.y;
        a1z += pa * xa1.z + pb * xb1.z; a1w += pa * xa1.w + pb * xb1.w;
    }

    // stash per-warp state
    int c0 = 4 * lane;
    s_acc[w][c0 + 0] = a0x; s_acc[w][c0 + 1] = a0y;
    s_acc[w][c0 + 2] = a0z; s_acc[w][c0 + 3] = a0w;
    s_acc[w][128 + c0 + 0] = a1x; s_acc[w][128 + c0 + 1] = a1y;
    s_acc[w][128 + c0 + 2] = a1z; s_acc[w][128 + c0 + 3] = a1w;
    if (lane == 0) { s_mx[w] = wmax; s_sm[w] = wsum; }
    __syncthreads();

    // combine 8 warps; tid == output column d
    float M = -INFINITY;
#pragma unroll
    for (int i = 0; i < 8; i++) M = fmaxf(M, s_mx[i]);
    if (M == -INFINITY) M = 0.f;   // empty-segment guard (matches reference)

    float total = 0.f, r = 0.f;
#pragma unroll
    for (int i = 0; i < 8; i++) {
        float f = __expf(s_mx[i] - M);   // exp(-inf - M) = 0 for idle warps
        total += s_sm[i] * f;
        r += s_acc[i][tid] * f;
    }
    g_qstar[(size_t)b * 512 + 256 + tid] = r / (total + 1e-16f);
}

// ---------------- final copy ---------------------------------------------
__global__ void k_out(float* __restrict__ out) {
    int i = blockIdx.x * blockDim.x + threadIdx.x;
    if (i < BSZ * 2 * DD) out[i] = g_qstar[i];
}

extern "C" void kernel_launch(void* const* d_in, const int* in_sizes, int n_in,
                              void* d_out, int out_size) {
    const float* x     = (const float*)d_in[0];
    const int*   batch = (const int*)d_in[2];
    const float* qs    = (const float*)d_in[3];
    const float* W_ih  = (const float*)d_in[4];
    const float* W_hh  = (const float*)d_in[5];
    const float* b_ih  = (const float*)d_in[6];
    const float* b_hh  = (const float*)d_in[7];

    k_init<<<2048, 256>>>(qs);
    k_seg<<<5, 256>>>(batch);

    dim3 gg(16, 16);
    for (int s = 0; s < STEPS; s++) {
        k_gemm_gates<<<gg, 256>>>(W_ih, W_hh, b_ih, b_hh);
        k_attn<<<BSZ, 256>>>(x);
    }
    k_out<<<2048, 256>>>((float*)d_out);
}